// round 14
// baseline (speedup 1.0000x reference)
#include <cuda_runtime.h>
#include <math.h>
#include <stdint.h>

// Problem constants
#define BB 2
#define SS 2048
#define DM 1024
#define NH 16
#define DK 64
#define BH (BB*NH)          // 32
#define M_ROWS (BB*SS)      // 4096

// Scratch (allocation-free rule: __device__ globals)
__device__ float g_Q[BH * SS * DK];    // (b,h,s,d) head-major
__device__ float g_K[BH * SS * DK];
__device__ float g_V[BH * SS * DK];
__device__ float g_ctx[M_ROWS * DM];   // (b,s,d_model)
__device__ float g_rowsum[BH * SS];    // per-row sum of exp(scores)

// ---------------------------------------------------------------------------
// tf32 helpers
// ---------------------------------------------------------------------------
__device__ __forceinline__ uint32_t f2tf32(float x) {
    uint32_t r;
    asm("cvt.rna.tf32.f32 %0, %1;" : "=r"(r) : "f"(x));
    return r;
}

__device__ __forceinline__ void mma_tf32(float* d,
                                         const uint32_t* a,
                                         const uint32_t* b)
{
    asm volatile(
        "mma.sync.aligned.m16n8k8.row.col.f32.tf32.tf32.f32 "
        "{%0,%1,%2,%3}, {%4,%5,%6,%7}, {%8,%9}, {%0,%1,%2,%3};\n"
        : "+f"(d[0]), "+f"(d[1]), "+f"(d[2]), "+f"(d[3])
        : "r"(a[0]), "r"(a[1]), "r"(a[2]), "r"(a[3]),
          "r"(b[0]), "r"(b[1]));
}

// ---------------------------------------------------------------------------
// Fused QKV projection (z selects q/k/v): C = X(4096x1024)@W(1024x1024)+b,
// head-major output. Block 128x128, BK=32, 256 thr, warp tile 64x32 (R7-proven).
// ---------------------------------------------------------------------------
__global__ __launch_bounds__(256) void qkv_kernel(
    const float* __restrict__ q_in, const float* __restrict__ k_in, const float* __restrict__ v_in,
    const float* __restrict__ Wq, const float* __restrict__ Wk, const float* __restrict__ Wv,
    const float* __restrict__ bq, const float* __restrict__ bk, const float* __restrict__ bv,
    float* __restrict__ Qo, float* __restrict__ Ko, float* __restrict__ Vo)
{
    __shared__ uint32_t As[128 * 36];   // [m][k] pad 36
    __shared__ uint32_t Bs[32 * 132];   // [k][n] pad 132

    const int z = blockIdx.z;
    const float* X = (z == 0) ? q_in : (z == 1) ? k_in : v_in;
    const float* W = (z == 0) ? Wq : (z == 1) ? Wk : Wv;
    const float* bias = (z == 0) ? bq : (z == 1) ? bk : bv;
    float* out = (z == 0) ? Qo : (z == 1) ? Ko : Vo;

    const int tid = threadIdx.x;
    const int lane = tid & 31;
    const int warp = tid >> 5;
    const int r = lane >> 2;      // 0..7
    const int c = lane & 3;       // 0..3
    const int wm = (warp >> 2) * 64;  // 0 or 64
    const int wn = (warp & 3) * 32;   // 0,32,64,96
    const int rowBase = blockIdx.y * 128;
    const int colBase = blockIdx.x * 128;

    float acc[4][4][4];
    #pragma unroll
    for (int i = 0; i < 4; i++)
        #pragma unroll
        for (int j = 0; j < 4; j++)
            #pragma unroll
            for (int k = 0; k < 4; k++) acc[i][j][k] = 0.0f;

    for (int k0 = 0; k0 < DM; k0 += 32) {
        #pragma unroll
        for (int cc = 0; cc < 4; cc++) {
            const int lin = tid + cc * 256;
            const int row = lin >> 3;
            const int kq = (lin & 7) * 4;
            float4 v = *reinterpret_cast<const float4*>(&X[(size_t)(rowBase + row) * DM + k0 + kq]);
            As[row * 36 + kq + 0] = f2tf32(v.x);
            As[row * 36 + kq + 1] = f2tf32(v.y);
            As[row * 36 + kq + 2] = f2tf32(v.z);
            As[row * 36 + kq + 3] = f2tf32(v.w);
        }
        #pragma unroll
        for (int cc = 0; cc < 4; cc++) {
            const int lin = tid + cc * 256;
            const int kr = lin >> 5;
            const int nq = (lin & 31) * 4;
            float4 v = *reinterpret_cast<const float4*>(&W[(size_t)(k0 + kr) * DM + colBase + nq]);
            Bs[kr * 132 + nq + 0] = f2tf32(v.x);
            Bs[kr * 132 + nq + 1] = f2tf32(v.y);
            Bs[kr * 132 + nq + 2] = f2tf32(v.z);
            Bs[kr * 132 + nq + 3] = f2tf32(v.w);
        }
        __syncthreads();

        #pragma unroll
        for (int kk = 0; kk < 32; kk += 8) {
            uint32_t afr[4][4], bfr[4][2];
            #pragma unroll
            for (int ma = 0; ma < 4; ma++) {
                const int m = wm + ma * 16 + r;
                afr[ma][0] = As[m * 36 + kk + c];
                afr[ma][1] = As[(m + 8) * 36 + kk + c];
                afr[ma][2] = As[m * 36 + kk + c + 4];
                afr[ma][3] = As[(m + 8) * 36 + kk + c + 4];
            }
            #pragma unroll
            for (int na = 0; na < 4; na++) {
                const int n = wn + na * 8 + r;
                bfr[na][0] = Bs[(kk + c) * 132 + n];
                bfr[na][1] = Bs[(kk + c + 4) * 132 + n];
            }
            #pragma unroll
            for (int ma = 0; ma < 4; ma++)
                #pragma unroll
                for (int na = 0; na < 4; na++)
                    mma_tf32(acc[ma][na], afr[ma], bfr[na]);
        }
        __syncthreads();
    }

    #pragma unroll
    for (int ma = 0; ma < 4; ma++) {
        #pragma unroll
        for (int na = 0; na < 4; na++) {
            const int n = colBase + wn + na * 8 + c * 2;
            const int h = n >> 6;
            const int d = n & 63;
            const float bx = bias[n];
            const float by = bias[n + 1];
            #pragma unroll
            for (int half = 0; half < 2; half++) {
                const int m = rowBase + wm + ma * 16 + r + half * 8;
                const int b = m >> 11;
                const int s = m & 2047;
                float2 v;
                v.x = acc[ma][na][half * 2 + 0] + bx;
                v.y = acc[ma][na][half * 2 + 1] + by;
                *reinterpret_cast<float2*>(&out[(((size_t)(b * NH + h) * SS + s) << 6) + d]) = v;
            }
        }
    }
}

// ---------------------------------------------------------------------------
// O projection: C = ctx(4096x1024)@Wo + bo, row-major out (R7-proven).
// Final store via st.cs (never re-read).
// ---------------------------------------------------------------------------
__global__ __launch_bounds__(256) void oproj_kernel(
    const float* __restrict__ X, const float* __restrict__ W,
    const float* __restrict__ bias, float* __restrict__ out)
{
    __shared__ uint32_t As[128 * 36];
    __shared__ uint32_t Bs[32 * 132];

    const int tid = threadIdx.x;
    const int lane = tid & 31;
    const int warp = tid >> 5;
    const int r = lane >> 2;
    const int c = lane & 3;
    const int wm = (warp >> 2) * 64;
    const int wn = (warp & 3) * 32;
    const int rowBase = blockIdx.y * 128;
    const int colBase = blockIdx.x * 128;

    float acc[4][4][4];
    #pragma unroll
    for (int i = 0; i < 4; i++)
        #pragma unroll
        for (int j = 0; j < 4; j++)
            #pragma unroll
            for (int k = 0; k < 4; k++) acc[i][j][k] = 0.0f;

    for (int k0 = 0; k0 < DM; k0 += 32) {
        #pragma unroll
        for (int cc = 0; cc < 4; cc++) {
            const int lin = tid + cc * 256;
            const int row = lin >> 3;
            const int kq = (lin & 7) * 4;
            float4 v = *reinterpret_cast<const float4*>(&X[(size_t)(rowBase + row) * DM + k0 + kq]);
            As[row * 36 + kq + 0] = f2tf32(v.x);
            As[row * 36 + kq + 1] = f2tf32(v.y);
            As[row * 36 + kq + 2] = f2tf32(v.z);
            As[row * 36 + kq + 3] = f2tf32(v.w);
        }
        #pragma unroll
        for (int cc = 0; cc < 4; cc++) {
            const int lin = tid + cc * 256;
            const int kr = lin >> 5;
            const int nq = (lin & 31) * 4;
            float4 v = *reinterpret_cast<const float4*>(&W[(size_t)(k0 + kr) * DM + colBase + nq]);
            Bs[kr * 132 + nq + 0] = f2tf32(v.x);
            Bs[kr * 132 + nq + 1] = f2tf32(v.y);
            Bs[kr * 132 + nq + 2] = f2tf32(v.z);
            Bs[kr * 132 + nq + 3] = f2tf32(v.w);
        }
        __syncthreads();

        #pragma unroll
        for (int kk = 0; kk < 32; kk += 8) {
            uint32_t afr[4][4], bfr[4][2];
            #pragma unroll
            for (int ma = 0; ma < 4; ma++) {
                const int m = wm + ma * 16 + r;
                afr[ma][0] = As[m * 36 + kk + c];
                afr[ma][1] = As[(m + 8) * 36 + kk + c];
                afr[ma][2] = As[m * 36 + kk + c + 4];
                afr[ma][3] = As[(m + 8) * 36 + kk + c + 4];
            }
            #pragma unroll
            for (int na = 0; na < 4; na++) {
                const int n = wn + na * 8 + r;
                bfr[na][0] = Bs[(kk + c) * 132 + n];
                bfr[na][1] = Bs[(kk + c + 4) * 132 + n];
            }
            #pragma unroll
            for (int ma = 0; ma < 4; ma++)
                #pragma unroll
                for (int na = 0; na < 4; na++)
                    mma_tf32(acc[ma][na], afr[ma], bfr[na]);
        }
        __syncthreads();
    }

    #pragma unroll
    for (int ma = 0; ma < 4; ma++) {
        #pragma unroll
        for (int na = 0; na < 4; na++) {
            const int n = colBase + wn + na * 8 + c * 2;
            const float bx = bias[n];
            const float by = bias[n + 1];
            #pragma unroll
            for (int half = 0; half < 2; half++) {
                const int m = rowBase + wm + ma * 16 + r + half * 8;
                float2 v;
                v.x = acc[ma][na][half * 2 + 0] + bx;
                v.y = acc[ma][na][half * 2 + 1] + by;
                __stcs(reinterpret_cast<float2*>(&out[(size_t)m * DM + n]), v);
            }
        }
    }
}

// ---------------------------------------------------------------------------
// Scores+exp: attn[bh][i][j] = exp(0.125 * dot(Q[bh][i], K[bh][j]))  (UNNORM)
// Accumulates per-row exp-sums into rowsum. 64x128 tiles for higher occupancy.
// 256 thr, warps 2m x 4n, warp tile 32x32.
// ---------------------------------------------------------------------------
__global__ __launch_bounds__(256) void scores_exp_kernel(
    const float* __restrict__ Q, const float* __restrict__ K,
    float* __restrict__ attn, float* __restrict__ rowsum)
{
    __shared__ uint32_t Qs[64 * 68];    // [i][d] pad 68
    __shared__ uint32_t Ks[128 * 68];   // [j][d] pad 68
    __shared__ float srow[64];

    const int bh = blockIdx.z;
    const float* Qh = Q + (size_t)bh * SS * DK;
    const float* Kh = K + (size_t)bh * SS * DK;

    const int tid = threadIdx.x;
    const int lane = tid & 31;
    const int warp = tid >> 5;
    const int r = lane >> 2;
    const int c = lane & 3;
    const int wm = (warp >> 2) * 32;    // 0 or 32
    const int wn = (warp & 3) * 32;     // 0,32,64,96
    const int iBase = blockIdx.y * 64;
    const int jBase = blockIdx.x * 128;

    if (tid < 64) srow[tid] = 0.0f;

    // Q tile: 64 x 64 = 1024 float4, 4/thread
    #pragma unroll
    for (int cc = 0; cc < 4; cc++) {
        const int lin = tid + cc * 256;
        const int row = lin >> 4;
        const int dq = (lin & 15) * 4;
        float4 qv = *reinterpret_cast<const float4*>(&Qh[(size_t)(iBase + row) * DK + dq]);
        Qs[row * 68 + dq + 0] = f2tf32(qv.x);
        Qs[row * 68 + dq + 1] = f2tf32(qv.y);
        Qs[row * 68 + dq + 2] = f2tf32(qv.z);
        Qs[row * 68 + dq + 3] = f2tf32(qv.w);
    }
    // K tile: 128 x 64 = 2048 float4, 8/thread
    #pragma unroll
    for (int cc = 0; cc < 8; cc++) {
        const int lin = tid + cc * 256;
        const int row = lin >> 4;
        const int dq = (lin & 15) * 4;
        float4 kv = *reinterpret_cast<const float4*>(&Kh[(size_t)(jBase + row) * DK + dq]);
        Ks[row * 68 + dq + 0] = f2tf32(kv.x);
        Ks[row * 68 + dq + 1] = f2tf32(kv.y);
        Ks[row * 68 + dq + 2] = f2tf32(kv.z);
        Ks[row * 68 + dq + 3] = f2tf32(kv.w);
    }
    __syncthreads();

    float acc[2][4][4];
    #pragma unroll
    for (int i = 0; i < 2; i++)
        #pragma unroll
        for (int j = 0; j < 4; j++)
            #pragma unroll
            for (int k = 0; k < 4; k++) acc[i][j][k] = 0.0f;

    #pragma unroll
    for (int kk = 0; kk < 64; kk += 8) {
        uint32_t afr[2][4], bfr[4][2];
        #pragma unroll
        for (int ma = 0; ma < 2; ma++) {
            const int m = wm + ma * 16 + r;
            afr[ma][0] = Qs[m * 68 + kk + c];
            afr[ma][1] = Qs[(m + 8) * 68 + kk + c];
            afr[ma][2] = Qs[m * 68 + kk + c + 4];
            afr[ma][3] = Qs[(m + 8) * 68 + kk + c + 4];
        }
        #pragma unroll
        for (int na = 0; na < 4; na++) {
            const int n = wn + na * 8 + r;
            bfr[na][0] = Ks[n * 68 + kk + c];
            bfr[na][1] = Ks[n * 68 + kk + c + 4];
        }
        #pragma unroll
        for (int ma = 0; ma < 2; ma++)
            #pragma unroll
            for (int na = 0; na < 4; na++)
                mma_tf32(acc[ma][na], afr[ma], bfr[na]);
    }

    const float scale = 0.125f;
    float rpart[2][2];
    rpart[0][0] = rpart[0][1] = rpart[1][0] = rpart[1][1] = 0.0f;

    #pragma unroll
    for (int ma = 0; ma < 2; ma++) {
        #pragma unroll
        for (int na = 0; na < 4; na++) {
            const int j = jBase + wn + na * 8 + c * 2;
            #pragma unroll
            for (int half = 0; half < 2; half++) {
                const int gi = iBase + wm + ma * 16 + r + half * 8;
                float2 v;
                v.x = __expf(acc[ma][na][half * 2 + 0] * scale);
                v.y = __expf(acc[ma][na][half * 2 + 1] * scale);
                *reinterpret_cast<float2*>(&attn[((size_t)bh * SS + gi) * SS + j]) = v;
                rpart[ma][half] += v.x + v.y;
            }
        }
    }

    #pragma unroll
    for (int ma = 0; ma < 2; ma++) {
        #pragma unroll
        for (int half = 0; half < 2; half++) {
            float p = rpart[ma][half];
            p += __shfl_xor_sync(0xFFFFFFFFu, p, 1);
            p += __shfl_xor_sync(0xFFFFFFFFu, p, 2);
            if (c == 0)
                atomicAdd(&srow[wm + ma * 16 + r + half * 8], p);
        }
    }
    __syncthreads();
    if (tid < 64)
        atomicAdd(&rowsum[(size_t)bh * SS + iBase + tid], srow[tid]);
}

// ---------------------------------------------------------------------------
// ctx + normalize: reads unnormalized exp-scores, scales by 1/rowsum, writes
// normalized attn IN PLACE (st.cs: never re-read), accumulates P@V (tf32 mma).
// Block 64 rows, BK=32, double-buffered smem + register prefetch (R7-proven).
// ---------------------------------------------------------------------------
__global__ __launch_bounds__(256) void ctx_kernel(
    const float* __restrict__ rowsum, float* __restrict__ attn,
    const float* __restrict__ V, float* __restrict__ ctx)
{
    __shared__ uint32_t As[2][64 * 36];   // [s][j] pad 36
    __shared__ uint32_t Vs[2][32 * 72];   // [j][d] pad 72
    __shared__ float s_inv[64];

    const int bh = blockIdx.y;
    const int b = bh >> 4;
    const int h = bh & 15;
    float* Ah = attn + (size_t)bh * SS * SS;
    const float* Vh = V + (size_t)bh * SS * DK;

    const int tid = threadIdx.x;
    const int lane = tid & 31;
    const int warp = tid >> 5;
    const int r = lane >> 2;
    const int c = lane & 3;
    const int wm = (warp >> 1) * 16;    // 0,16,32,48
    const int wn = (warp & 1) * 32;     // 0,32
    const int iBase = blockIdx.x * 64;

    if (tid < 64)
        s_inv[tid] = 1.0f / rowsum[(size_t)bh * SS + iBase + tid];

    float4 aR[2], vR[2];
    #pragma unroll
    for (int cc = 0; cc < 2; cc++) {
        const int lin = tid + cc * 256;
        const int row = lin >> 3;
        const int kq = (lin & 7) * 4;
        aR[cc] = *reinterpret_cast<const float4*>(&Ah[(size_t)(iBase + row) * SS + kq]);
    }
    #pragma unroll
    for (int cc = 0; cc < 2; cc++) {
        const int lin = tid + cc * 256;
        const int kr = lin >> 4;
        const int nq = (lin & 15) * 4;
        vR[cc] = *reinterpret_cast<const float4*>(&Vh[(size_t)kr * DK + nq]);
    }
    __syncthreads();   // s_inv ready

    float acc[4][4];
    #pragma unroll
    for (int j = 0; j < 4; j++)
        #pragma unroll
        for (int k = 0; k < 4; k++) acc[j][k] = 0.0f;

    int buf = 0;
    for (int k0 = 0; k0 < SS; k0 += 32) {
        #pragma unroll
        for (int cc = 0; cc < 2; cc++) {
            const int lin = tid + cc * 256;
            const int row = lin >> 3;
            const int kq = (lin & 7) * 4;
            const float inv = s_inv[row];
            float4 p;
            p.x = aR[cc].x * inv; p.y = aR[cc].y * inv;
            p.z = aR[cc].z * inv; p.w = aR[cc].w * inv;
            __stcs(reinterpret_cast<float4*>(&Ah[(size_t)(iBase + row) * SS + k0 + kq]), p);
            As[buf][row * 36 + kq + 0] = f2tf32(p.x);
            As[buf][row * 36 + kq + 1] = f2tf32(p.y);
            As[buf][row * 36 + kq + 2] = f2tf32(p.z);
            As[buf][row * 36 + kq + 3] = f2tf32(p.w);
        }
        #pragma unroll
        for (int cc = 0; cc < 2; cc++) {
            const int lin = tid + cc * 256;
            const int kr = lin >> 4;
            const int nq = (lin & 15) * 4;
            Vs[buf][kr * 72 + nq + 0] = f2tf32(vR[cc].x);
            Vs[buf][kr * 72 + nq + 1] = f2tf32(vR[cc].y);
            Vs[buf][kr * 72 + nq + 2] = f2tf32(vR[cc].z);
            Vs[buf][kr * 72 + nq + 3] = f2tf32(vR[cc].w);
        }
        __syncthreads();

        if (k0 + 32 < SS) {
            #pragma unroll
            for (int cc = 0; cc < 2; cc++) {
                const int lin = tid + cc * 256;
                const int row = lin >> 3;
                const int kq = (lin & 7) * 4;
                aR[cc] = *reinterpret_cast<const float4*>(&Ah[(size_t)(iBase + row) * SS + (k0 + 32) + kq]);
            }
            #pragma unroll
            for (int cc = 0; cc < 2; cc++) {
                const int lin = tid + cc * 256;
                const int kr = lin >> 4;
                const int nq = (lin & 15) * 4;
                vR[cc] = *reinterpret_cast<const float4*>(&Vh[(size_t)(k0 + 32 + kr) * DK + nq]);
            }
        }

        #pragma unroll
        for (int kk = 0; kk < 32; kk += 8) {
            uint32_t afr[4], bfr[4][2];
            const int m = wm + r;
            afr[0] = As[buf][m * 36 + kk + c];
            afr[1] = As[buf][(m + 8) * 36 + kk + c];
            afr[2] = As[buf][m * 36 + kk + c + 4];
            afr[3] = As[buf][(m + 8) * 36 + kk + c + 4];
            #pragma unroll
            for (int na = 0; na < 4; na++) {
                const int n = wn + na * 8 + r;
                bfr[na][0] = Vs[buf][(kk + c) * 72 + n];
                bfr[na][1] = Vs[buf][(kk + c + 4) * 72 + n];
            }
            #pragma unroll
            for (int na = 0; na < 4; na++)
                mma_tf32(acc[na], afr, bfr[na]);
        }
        buf ^= 1;
    }

    #pragma unroll
    for (int na = 0; na < 4; na++) {
        const int d = wn + na * 8 + c * 2;
        #pragma unroll
        for (int half = 0; half < 2; half++) {
            const int s = iBase + wm + r + half * 8;
            float2 v;
            v.x = acc[na][half * 2 + 0];
            v.y = acc[na][half * 2 + 1];
            __stcs(reinterpret_cast<float2*>(&ctx[((size_t)(b * SS + s)) * DM + h * DK + d]), v);
        }
    }
}

// ---------------------------------------------------------------------------
extern "C" void kernel_launch(void* const* d_in, const int* in_sizes, int n_in,
                              void* d_out, int out_size)
{
    const float* query = (const float*)d_in[0];
    const float* key   = (const float*)d_in[1];
    const float* value = (const float*)d_in[2];
    const float* Wq    = (const float*)d_in[3];
    const float* bq    = (const float*)d_in[4];
    const float* Wk    = (const float*)d_in[5];
    const float* bk    = (const float*)d_in[6];
    const float* Wv    = (const float*)d_in[7];
    const float* bv    = (const float*)d_in[8];
    const float* Wo    = (const float*)d_in[9];
    const float* bo    = (const float*)d_in[10];

    float* out_ptr  = (float*)d_out;                       // (B,S,D_MODEL)
    float* attn_ptr = (float*)d_out + (size_t)M_ROWS * DM; // (B,H,S,S)

    float* Qp;  cudaGetSymbolAddress((void**)&Qp,  g_Q);
    float* Kp;  cudaGetSymbolAddress((void**)&Kp,  g_K);
    float* Vp;  cudaGetSymbolAddress((void**)&Vp,  g_V);
    float* Cp;  cudaGetSymbolAddress((void**)&Cp,  g_ctx);
    float* Rp;  cudaGetSymbolAddress((void**)&Rp,  g_rowsum);

    cudaMemsetAsync(Rp, 0, (size_t)BH * SS * sizeof(float));

    dim3 gQKV(DM / 128, M_ROWS / 128, 3);     // (8, 32, 3)
    qkv_kernel<<<gQKV, 256>>>(query, key, value, Wq, Wk, Wv, bq, bk, bv, Qp, Kp, Vp);

    dim3 gScores(SS / 128, SS / 64, BH);      // (16, 32, 32)
    scores_exp_kernel<<<gScores, 256>>>(Qp, Kp, attn_ptr, Rp);

    dim3 gCtx(SS / 64, BH);                   // (32, 32)
    ctx_kernel<<<gCtx, 256>>>(Rp, attn_ptr, Vp, Cp);

    dim3 gO(DM / 128, M_ROWS / 128);          // (8, 32)
    oproj_kernel<<<gO, 256>>>(Cp, Wo, bo, out_ptr);
}

// round 15
// speedup vs baseline: 1.0792x; 1.0792x over previous
#include <cuda_runtime.h>
#include <math.h>
#include <stdint.h>

// Problem constants
#define BB 2
#define SS 2048
#define DM 1024
#define NH 16
#define DK 64
#define BH (BB*NH)          // 32
#define M_ROWS (BB*SS)      // 4096

// Scratch (allocation-free rule: __device__ globals)
__device__ float g_Q[BH * SS * DK];    // (b,h,s,d) head-major
__device__ float g_K[BH * SS * DK];
__device__ float g_V[BH * SS * DK];
__device__ float g_ctx[M_ROWS * DM];   // (b,s,d_model)
__device__ float g_rowsum[BH * SS];    // per-row sum of exp(scores)

// ---------------------------------------------------------------------------
// tf32 helpers
// ---------------------------------------------------------------------------
__device__ __forceinline__ uint32_t f2tf32(float x) {
    uint32_t r;
    asm("cvt.rna.tf32.f32 %0, %1;" : "=r"(r) : "f"(x));
    return r;
}

__device__ __forceinline__ void mma_tf32(float* d,
                                         const uint32_t* a,
                                         const uint32_t* b)
{
    asm volatile(
        "mma.sync.aligned.m16n8k8.row.col.f32.tf32.tf32.f32 "
        "{%0,%1,%2,%3}, {%4,%5,%6,%7}, {%8,%9}, {%0,%1,%2,%3};\n"
        : "+f"(d[0]), "+f"(d[1]), "+f"(d[2]), "+f"(d[3])
        : "r"(a[0]), "r"(a[1]), "r"(a[2]), "r"(a[3]),
          "r"(b[0]), "r"(b[1]));
}

// ---------------------------------------------------------------------------
// Fused QKV projection (z selects q/k/v): C = X(4096x1024)@W(1024x1024)+b,
// head-major output. Block 128x128, BK=32, 256 thr, warp tile 64x32 (R7-proven).
// ---------------------------------------------------------------------------
__global__ __launch_bounds__(256) void qkv_kernel(
    const float* __restrict__ q_in, const float* __restrict__ k_in, const float* __restrict__ v_in,
    const float* __restrict__ Wq, const float* __restrict__ Wk, const float* __restrict__ Wv,
    const float* __restrict__ bq, const float* __restrict__ bk, const float* __restrict__ bv,
    float* __restrict__ Qo, float* __restrict__ Ko, float* __restrict__ Vo)
{
    __shared__ uint32_t As[128 * 36];   // [m][k] pad 36
    __shared__ uint32_t Bs[32 * 132];   // [k][n] pad 132

    const int z = blockIdx.z;
    const float* X = (z == 0) ? q_in : (z == 1) ? k_in : v_in;
    const float* W = (z == 0) ? Wq : (z == 1) ? Wk : Wv;
    const float* bias = (z == 0) ? bq : (z == 1) ? bk : bv;
    float* out = (z == 0) ? Qo : (z == 1) ? Ko : Vo;

    const int tid = threadIdx.x;
    const int lane = tid & 31;
    const int warp = tid >> 5;
    const int r = lane >> 2;      // 0..7
    const int c = lane & 3;       // 0..3
    const int wm = (warp >> 2) * 64;  // 0 or 64
    const int wn = (warp & 3) * 32;   // 0,32,64,96
    const int rowBase = blockIdx.y * 128;
    const int colBase = blockIdx.x * 128;

    float acc[4][4][4];
    #pragma unroll
    for (int i = 0; i < 4; i++)
        #pragma unroll
        for (int j = 0; j < 4; j++)
            #pragma unroll
            for (int k = 0; k < 4; k++) acc[i][j][k] = 0.0f;

    for (int k0 = 0; k0 < DM; k0 += 32) {
        #pragma unroll
        for (int cc = 0; cc < 4; cc++) {
            const int lin = tid + cc * 256;
            const int row = lin >> 3;
            const int kq = (lin & 7) * 4;
            float4 v = *reinterpret_cast<const float4*>(&X[(size_t)(rowBase + row) * DM + k0 + kq]);
            As[row * 36 + kq + 0] = f2tf32(v.x);
            As[row * 36 + kq + 1] = f2tf32(v.y);
            As[row * 36 + kq + 2] = f2tf32(v.z);
            As[row * 36 + kq + 3] = f2tf32(v.w);
        }
        #pragma unroll
        for (int cc = 0; cc < 4; cc++) {
            const int lin = tid + cc * 256;
            const int kr = lin >> 5;
            const int nq = (lin & 31) * 4;
            float4 v = *reinterpret_cast<const float4*>(&W[(size_t)(k0 + kr) * DM + colBase + nq]);
            Bs[kr * 132 + nq + 0] = f2tf32(v.x);
            Bs[kr * 132 + nq + 1] = f2tf32(v.y);
            Bs[kr * 132 + nq + 2] = f2tf32(v.z);
            Bs[kr * 132 + nq + 3] = f2tf32(v.w);
        }
        __syncthreads();

        #pragma unroll
        for (int kk = 0; kk < 32; kk += 8) {
            uint32_t afr[4][4], bfr[4][2];
            #pragma unroll
            for (int ma = 0; ma < 4; ma++) {
                const int m = wm + ma * 16 + r;
                afr[ma][0] = As[m * 36 + kk + c];
                afr[ma][1] = As[(m + 8) * 36 + kk + c];
                afr[ma][2] = As[m * 36 + kk + c + 4];
                afr[ma][3] = As[(m + 8) * 36 + kk + c + 4];
            }
            #pragma unroll
            for (int na = 0; na < 4; na++) {
                const int n = wn + na * 8 + r;
                bfr[na][0] = Bs[(kk + c) * 132 + n];
                bfr[na][1] = Bs[(kk + c + 4) * 132 + n];
            }
            #pragma unroll
            for (int ma = 0; ma < 4; ma++)
                #pragma unroll
                for (int na = 0; na < 4; na++)
                    mma_tf32(acc[ma][na], afr[ma], bfr[na]);
        }
        __syncthreads();
    }

    #pragma unroll
    for (int ma = 0; ma < 4; ma++) {
        #pragma unroll
        for (int na = 0; na < 4; na++) {
            const int n = colBase + wn + na * 8 + c * 2;
            const int h = n >> 6;
            const int d = n & 63;
            const float bx = bias[n];
            const float by = bias[n + 1];
            #pragma unroll
            for (int half = 0; half < 2; half++) {
                const int m = rowBase + wm + ma * 16 + r + half * 8;
                const int b = m >> 11;
                const int s = m & 2047;
                float2 v;
                v.x = acc[ma][na][half * 2 + 0] + bx;
                v.y = acc[ma][na][half * 2 + 1] + by;
                *reinterpret_cast<float2*>(&out[(((size_t)(b * NH + h) * SS + s) << 6) + d]) = v;
            }
        }
    }
}

// ---------------------------------------------------------------------------
// O projection: C = ctx(4096x1024)@Wo + bo, row-major out (R7-proven).
// ---------------------------------------------------------------------------
__global__ __launch_bounds__(256) void oproj_kernel(
    const float* __restrict__ X, const float* __restrict__ W,
    const float* __restrict__ bias, float* __restrict__ out)
{
    __shared__ uint32_t As[128 * 36];
    __shared__ uint32_t Bs[32 * 132];

    const int tid = threadIdx.x;
    const int lane = tid & 31;
    const int warp = tid >> 5;
    const int r = lane >> 2;
    const int c = lane & 3;
    const int wm = (warp >> 2) * 64;
    const int wn = (warp & 3) * 32;
    const int rowBase = blockIdx.y * 128;
    const int colBase = blockIdx.x * 128;

    float acc[4][4][4];
    #pragma unroll
    for (int i = 0; i < 4; i++)
        #pragma unroll
        for (int j = 0; j < 4; j++)
            #pragma unroll
            for (int k = 0; k < 4; k++) acc[i][j][k] = 0.0f;

    for (int k0 = 0; k0 < DM; k0 += 32) {
        #pragma unroll
        for (int cc = 0; cc < 4; cc++) {
            const int lin = tid + cc * 256;
            const int row = lin >> 3;
            const int kq = (lin & 7) * 4;
            float4 v = *reinterpret_cast<const float4*>(&X[(size_t)(rowBase + row) * DM + k0 + kq]);
            As[row * 36 + kq + 0] = f2tf32(v.x);
            As[row * 36 + kq + 1] = f2tf32(v.y);
            As[row * 36 + kq + 2] = f2tf32(v.z);
            As[row * 36 + kq + 3] = f2tf32(v.w);
        }
        #pragma unroll
        for (int cc = 0; cc < 4; cc++) {
            const int lin = tid + cc * 256;
            const int kr = lin >> 5;
            const int nq = (lin & 31) * 4;
            float4 v = *reinterpret_cast<const float4*>(&W[(size_t)(k0 + kr) * DM + colBase + nq]);
            Bs[kr * 132 + nq + 0] = f2tf32(v.x);
            Bs[kr * 132 + nq + 1] = f2tf32(v.y);
            Bs[kr * 132 + nq + 2] = f2tf32(v.z);
            Bs[kr * 132 + nq + 3] = f2tf32(v.w);
        }
        __syncthreads();

        #pragma unroll
        for (int kk = 0; kk < 32; kk += 8) {
            uint32_t afr[4][4], bfr[4][2];
            #pragma unroll
            for (int ma = 0; ma < 4; ma++) {
                const int m = wm + ma * 16 + r;
                afr[ma][0] = As[m * 36 + kk + c];
                afr[ma][1] = As[(m + 8) * 36 + kk + c];
                afr[ma][2] = As[m * 36 + kk + c + 4];
                afr[ma][3] = As[(m + 8) * 36 + kk + c + 4];
            }
            #pragma unroll
            for (int na = 0; na < 4; na++) {
                const int n = wn + na * 8 + r;
                bfr[na][0] = Bs[(kk + c) * 132 + n];
                bfr[na][1] = Bs[(kk + c + 4) * 132 + n];
            }
            #pragma unroll
            for (int ma = 0; ma < 4; ma++)
                #pragma unroll
                for (int na = 0; na < 4; na++)
                    mma_tf32(acc[ma][na], afr[ma], bfr[na]);
        }
        __syncthreads();
    }

    #pragma unroll
    for (int ma = 0; ma < 4; ma++) {
        #pragma unroll
        for (int na = 0; na < 4; na++) {
            const int n = colBase + wn + na * 8 + c * 2;
            const float bx = bias[n];
            const float by = bias[n + 1];
            #pragma unroll
            for (int half = 0; half < 2; half++) {
                const int m = rowBase + wm + ma * 16 + r + half * 8;
                float2 v;
                v.x = acc[ma][na][half * 2 + 0] + bx;
                v.y = acc[ma][na][half * 2 + 1] + by;
                *reinterpret_cast<float2*>(&out[(size_t)m * DM + n]) = v;
            }
        }
    }
}

// ---------------------------------------------------------------------------
// Scores+exp: attn[bh][i][j] = exp(0.125 * dot(Q[bh][i], K[bh][j]))  (UNNORM)
// Accumulates per-row exp-sums into rowsum. 128x128 tiles (R7-proven).
// ---------------------------------------------------------------------------
__global__ __launch_bounds__(256) void scores_exp_kernel(
    const float* __restrict__ Q, const float* __restrict__ K,
    float* __restrict__ attn, float* __restrict__ rowsum)
{
    __shared__ uint32_t Qs[128 * 68];   // [i][d] pad 68
    __shared__ uint32_t Ks[128 * 68];   // [j][d] pad 68
    __shared__ float srow[128];

    const int bh = blockIdx.z;
    const float* Qh = Q + (size_t)bh * SS * DK;
    const float* Kh = K + (size_t)bh * SS * DK;

    const int tid = threadIdx.x;
    const int lane = tid & 31;
    const int warp = tid >> 5;
    const int r = lane >> 2;
    const int c = lane & 3;
    const int wm = (warp >> 2) * 64;
    const int wn = (warp & 3) * 32;
    const int iBase = blockIdx.y * 128;
    const int jBase = blockIdx.x * 128;

    if (tid < 128) srow[tid] = 0.0f;

    #pragma unroll
    for (int cc = 0; cc < 8; cc++) {
        const int lin = tid + cc * 256;
        const int row = lin >> 4;
        const int dq = (lin & 15) * 4;
        float4 qv = *reinterpret_cast<const float4*>(&Qh[(size_t)(iBase + row) * DK + dq]);
        Qs[row * 68 + dq + 0] = f2tf32(qv.x);
        Qs[row * 68 + dq + 1] = f2tf32(qv.y);
        Qs[row * 68 + dq + 2] = f2tf32(qv.z);
        Qs[row * 68 + dq + 3] = f2tf32(qv.w);
        float4 kv = *reinterpret_cast<const float4*>(&Kh[(size_t)(jBase + row) * DK + dq]);
        Ks[row * 68 + dq + 0] = f2tf32(kv.x);
        Ks[row * 68 + dq + 1] = f2tf32(kv.y);
        Ks[row * 68 + dq + 2] = f2tf32(kv.z);
        Ks[row * 68 + dq + 3] = f2tf32(kv.w);
    }
    __syncthreads();

    float acc[4][4][4];
    #pragma unroll
    for (int i = 0; i < 4; i++)
        #pragma unroll
        for (int j = 0; j < 4; j++)
            #pragma unroll
            for (int k = 0; k < 4; k++) acc[i][j][k] = 0.0f;

    #pragma unroll
    for (int kk = 0; kk < 64; kk += 8) {
        uint32_t afr[4][4], bfr[4][2];
        #pragma unroll
        for (int ma = 0; ma < 4; ma++) {
            const int m = wm + ma * 16 + r;
            afr[ma][0] = Qs[m * 68 + kk + c];
            afr[ma][1] = Qs[(m + 8) * 68 + kk + c];
            afr[ma][2] = Qs[m * 68 + kk + c + 4];
            afr[ma][3] = Qs[(m + 8) * 68 + kk + c + 4];
        }
        #pragma unroll
        for (int na = 0; na < 4; na++) {
            const int n = wn + na * 8 + r;
            bfr[na][0] = Ks[n * 68 + kk + c];
            bfr[na][1] = Ks[n * 68 + kk + c + 4];
        }
        #pragma unroll
        for (int ma = 0; ma < 4; ma++)
            #pragma unroll
            for (int na = 0; na < 4; na++)
                mma_tf32(acc[ma][na], afr[ma], bfr[na]);
    }

    const float scale = 0.125f;
    float rpart[4][2];
    #pragma unroll
    for (int ma = 0; ma < 4; ma++)
        #pragma unroll
        for (int half = 0; half < 2; half++) rpart[ma][half] = 0.0f;

    #pragma unroll
    for (int ma = 0; ma < 4; ma++) {
        #pragma unroll
        for (int na = 0; na < 4; na++) {
            const int j = jBase + wn + na * 8 + c * 2;
            #pragma unroll
            for (int half = 0; half < 2; half++) {
                const int gi = iBase + wm + ma * 16 + r + half * 8;
                float2 v;
                v.x = __expf(acc[ma][na][half * 2 + 0] * scale);
                v.y = __expf(acc[ma][na][half * 2 + 1] * scale);
                *reinterpret_cast<float2*>(&attn[((size_t)bh * SS + gi) * SS + j]) = v;
                rpart[ma][half] += v.x + v.y;
            }
        }
    }

    #pragma unroll
    for (int ma = 0; ma < 4; ma++) {
        #pragma unroll
        for (int half = 0; half < 2; half++) {
            float p = rpart[ma][half];
            p += __shfl_xor_sync(0xFFFFFFFFu, p, 1);
            p += __shfl_xor_sync(0xFFFFFFFFu, p, 2);
            if (c == 0)
                atomicAdd(&srow[wm + ma * 16 + r + half * 8], p);
        }
    }
    __syncthreads();
    if (tid < 128)
        atomicAdd(&rowsum[(size_t)bh * SS + iBase + tid], srow[tid]);
}

// ---------------------------------------------------------------------------
// ctx + normalize: reads unnormalized exp-scores (__ldcs: read-once stream),
// scales by 1/rowsum, writes normalized attn IN PLACE (__stcs: never re-read),
// accumulates P@V (tf32 mma). Block 64 rows, BK=32, double-buffered smem +
// register prefetch (R7-proven structure; only cache hints added).
// ---------------------------------------------------------------------------
__global__ __launch_bounds__(256) void ctx_kernel(
    const float* __restrict__ rowsum, float* __restrict__ attn,
    const float* __restrict__ V, float* __restrict__ ctx)
{
    __shared__ uint32_t As[2][64 * 36];   // [s][j] pad 36
    __shared__ uint32_t Vs[2][32 * 72];   // [j][d] pad 72
    __shared__ float s_inv[64];

    const int bh = blockIdx.y;
    const int b = bh >> 4;
    const int h = bh & 15;
    float* Ah = attn + (size_t)bh * SS * SS;
    const float* Vh = V + (size_t)bh * SS * DK;

    const int tid = threadIdx.x;
    const int lane = tid & 31;
    const int warp = tid >> 5;
    const int r = lane >> 2;
    const int c = lane & 3;
    const int wm = (warp >> 1) * 16;    // 0,16,32,48
    const int wn = (warp & 1) * 32;     // 0,32
    const int iBase = blockIdx.x * 64;

    if (tid < 64)
        s_inv[tid] = 1.0f / rowsum[(size_t)bh * SS + iBase + tid];

    float4 aR[2], vR[2];
    #pragma unroll
    for (int cc = 0; cc < 2; cc++) {
        const int lin = tid + cc * 256;
        const int row = lin >> 3;
        const int kq = (lin & 7) * 4;
        aR[cc] = __ldcs(reinterpret_cast<const float4*>(&Ah[(size_t)(iBase + row) * SS + kq]));
    }
    #pragma unroll
    for (int cc = 0; cc < 2; cc++) {
        const int lin = tid + cc * 256;
        const int kr = lin >> 4;
        const int nq = (lin & 15) * 4;
        vR[cc] = *reinterpret_cast<const float4*>(&Vh[(size_t)kr * DK + nq]);
    }
    __syncthreads();   // s_inv ready

    float acc[4][4];
    #pragma unroll
    for (int j = 0; j < 4; j++)
        #pragma unroll
        for (int k = 0; k < 4; k++) acc[j][k] = 0.0f;

    int buf = 0;
    for (int k0 = 0; k0 < SS; k0 += 32) {
        #pragma unroll
        for (int cc = 0; cc < 2; cc++) {
            const int lin = tid + cc * 256;
            const int row = lin >> 3;
            const int kq = (lin & 7) * 4;
            const float inv = s_inv[row];
            float4 p;
            p.x = aR[cc].x * inv; p.y = aR[cc].y * inv;
            p.z = aR[cc].z * inv; p.w = aR[cc].w * inv;
            __stcs(reinterpret_cast<float4*>(&Ah[(size_t)(iBase + row) * SS + k0 + kq]), p);
            As[buf][row * 36 + kq + 0] = f2tf32(p.x);
            As[buf][row * 36 + kq + 1] = f2tf32(p.y);
            As[buf][row * 36 + kq + 2] = f2tf32(p.z);
            As[buf][row * 36 + kq + 3] = f2tf32(p.w);
        }
        #pragma unroll
        for (int cc = 0; cc < 2; cc++) {
            const int lin = tid + cc * 256;
            const int kr = lin >> 4;
            const int nq = (lin & 15) * 4;
            Vs[buf][kr * 72 + nq + 0] = f2tf32(vR[cc].x);
            Vs[buf][kr * 72 + nq + 1] = f2tf32(vR[cc].y);
            Vs[buf][kr * 72 + nq + 2] = f2tf32(vR[cc].z);
            Vs[buf][kr * 72 + nq + 3] = f2tf32(vR[cc].w);
        }
        __syncthreads();

        if (k0 + 32 < SS) {
            #pragma unroll
            for (int cc = 0; cc < 2; cc++) {
                const int lin = tid + cc * 256;
                const int row = lin >> 3;
                const int kq = (lin & 7) * 4;
                aR[cc] = __ldcs(reinterpret_cast<const float4*>(&Ah[(size_t)(iBase + row) * SS + (k0 + 32) + kq]));
            }
            #pragma unroll
            for (int cc = 0; cc < 2; cc++) {
                const int lin = tid + cc * 256;
                const int kr = lin >> 4;
                const int nq = (lin & 15) * 4;
                vR[cc] = *reinterpret_cast<const float4*>(&Vh[(size_t)(k0 + 32 + kr) * DK + nq]);
            }
        }

        #pragma unroll
        for (int kk = 0; kk < 32; kk += 8) {
            uint32_t afr[4], bfr[4][2];
            const int m = wm + r;
            afr[0] = As[buf][m * 36 + kk + c];
            afr[1] = As[buf][(m + 8) * 36 + kk + c];
            afr[2] = As[buf][m * 36 + kk + c + 4];
            afr[3] = As[buf][(m + 8) * 36 + kk + c + 4];
            #pragma unroll
            for (int na = 0; na < 4; na++) {
                const int n = wn + na * 8 + r;
                bfr[na][0] = Vs[buf][(kk + c) * 72 + n];
                bfr[na][1] = Vs[buf][(kk + c + 4) * 72 + n];
            }
            #pragma unroll
            for (int na = 0; na < 4; na++)
                mma_tf32(acc[na], afr, bfr[na]);
        }
        buf ^= 1;
    }

    #pragma unroll
    for (int na = 0; na < 4; na++) {
        const int d = wn + na * 8 + c * 2;
        #pragma unroll
        for (int half = 0; half < 2; half++) {
            const int s = iBase + wm + r + half * 8;
            float2 v;
            v.x = acc[na][half * 2 + 0];
            v.y = acc[na][half * 2 + 1];
            *reinterpret_cast<float2*>(&ctx[((size_t)(b * SS + s)) * DM + h * DK + d]) = v;
        }
    }
}

// ---------------------------------------------------------------------------
extern "C" void kernel_launch(void* const* d_in, const int* in_sizes, int n_in,
                              void* d_out, int out_size)
{
    const float* query = (const float*)d_in[0];
    const float* key   = (const float*)d_in[1];
    const float* value = (const float*)d_in[2];
    const float* Wq    = (const float*)d_in[3];
    const float* bq    = (const float*)d_in[4];
    const float* Wk    = (const float*)d_in[5];
    const float* bk    = (const float*)d_in[6];
    const float* Wv    = (const float*)d_in[7];
    const float* bv    = (const float*)d_in[8];
    const float* Wo    = (const float*)d_in[9];
    const float* bo    = (const float*)d_in[10];

    float* out_ptr  = (float*)d_out;                       // (B,S,D_MODEL)
    float* attn_ptr = (float*)d_out + (size_t)M_ROWS * DM; // (B,H,S,S)

    float* Qp;  cudaGetSymbolAddress((void**)&Qp,  g_Q);
    float* Kp;  cudaGetSymbolAddress((void**)&Kp,  g_K);
    float* Vp;  cudaGetSymbolAddress((void**)&Vp,  g_V);
    float* Cp;  cudaGetSymbolAddress((void**)&Cp,  g_ctx);
    float* Rp;  cudaGetSymbolAddress((void**)&Rp,  g_rowsum);

    cudaMemsetAsync(Rp, 0, (size_t)BH * SS * sizeof(float));

    dim3 gQKV(DM / 128, M_ROWS / 128, 3);     // (8, 32, 3)
    qkv_kernel<<<gQKV, 256>>>(query, key, value, Wq, Wk, Wv, bq, bk, bv, Qp, Kp, Vp);

    dim3 gScores(SS / 128, SS / 128, BH);     // (16, 16, 32)
    scores_exp_kernel<<<gScores, 256>>>(Qp, Kp, attn_ptr, Rp);

    dim3 gCtx(SS / 64, BH);                   // (32, 32)
    ctx_kernel<<<gCtx, 256>>>(Rp, attn_ptr, Vp, Cp);

    dim3 gO(DM / 128, M_ROWS / 128);          // (8, 32)
    oproj_kernel<<<gO, 256>>>(Cp, Wo, bo, out_ptr);
}